// round 5
// baseline (speedup 1.0000x reference)
#include <cuda_runtime.h>

// topk_mean (k=2) segment pooling.
// h: [BS, SEQ, EMB] fp32, patch_ids: [BS, SEQ] int32 sorted ascending per batch.
// out: [BS, PNUM, EMB] fp32.
// Semantics (faithful to reference tie-masking loop):
//   max1 = segment max; max2 = max over values strictly != max1 (or -1e9 if none)
//   count==0 -> 0 ; count==1 -> max1 ; count>=2 -> (max1 + max2)/2

#define BS   8
#define SEQ  4096
#define EMB  512
#define PNUM 1024
#define EV4  (EMB / 4)          /* 128 float4 per row */
#define NEG_INF_V (-1.0e9f)

// Scratch: starts[b][p] = first token index t with patch_ids[b][t] >= p.
// starts[b][PNUM] = SEQ. No device allocation allowed -> __device__ global.
__device__ int g_starts[BS * (PNUM + 1)];

__global__ void starts_kernel(const int* __restrict__ pid) {
    const int b = blockIdx.y;
    const int t = blockIdx.x * blockDim.x + threadIdx.x;
    if (t >= SEQ) return;
    const int* __restrict__ p = pid + b * SEQ;
    int* __restrict__ st = g_starts + b * (PNUM + 1);

    const int cur  = p[t];
    const int prev = (t == 0) ? -1 : p[t - 1];
    for (int q = prev + 1; q <= cur; ++q) st[q] = t;
    if (t == SEQ - 1) {
        for (int q = cur + 1; q <= PNUM; ++q) st[q] = SEQ;
    }
}

// Branchless running top-2 with tie-skip (v == m1 leaves m2 unchanged).
// Invariant m2 < m1 (strict) except both -inf at init, so on v > m1 the
// demoted value is exactly old m1.
__device__ __forceinline__ void upd1(float v, float& m1, float& m2) {
    const float nm2 = (v > m1) ? m1 : ((v < m1) ? fmaxf(m2, v) : m2);
    m1 = fmaxf(m1, v);
    m2 = nm2;
}

__device__ __forceinline__ void upd4(const float4 v, float4& m1, float4& m2) {
    upd1(v.x, m1.x, m2.x);
    upd1(v.y, m1.y, m2.y);
    upd1(v.z, m1.z, m2.z);
    upd1(v.w, m1.w, m2.w);
}

__global__ __launch_bounds__(128)
void pool_kernel(const float4* __restrict__ h4, float4* __restrict__ out4) {
    const int p = blockIdx.x;
    const int b = blockIdx.y;
    const int* __restrict__ st = g_starts + b * (PNUM + 1);
    const int start = st[p];
    const int cnt   = st[p + 1] - start;

    float4* __restrict__ o =
        out4 + ((size_t)(b * PNUM + p)) * EV4 + threadIdx.x;

    if (cnt == 0) {
        *o = make_float4(0.f, 0.f, 0.f, 0.f);
        return;
    }

    const float4* __restrict__ hb =
        h4 + ((size_t)b * SEQ + start) * EV4 + threadIdx.x;

    float4 m1 = make_float4(-INFINITY, -INFINITY, -INFINITY, -INFINITY);
    float4 m2 = m1;

    int t = 0;
    // 4-wide body: 4 independent LDG.128 in flight per trip (MLP=4)
    #pragma unroll 1
    for (; t + 4 <= cnt; t += 4) {
        const float4 v0 = __ldcs(&hb[(size_t)(t + 0) * EV4]);
        const float4 v1 = __ldcs(&hb[(size_t)(t + 1) * EV4]);
        const float4 v2 = __ldcs(&hb[(size_t)(t + 2) * EV4]);
        const float4 v3 = __ldcs(&hb[(size_t)(t + 3) * EV4]);
        upd4(v0, m1, m2);
        upd4(v1, m1, m2);
        upd4(v2, m1, m2);
        upd4(v3, m1, m2);
    }
    // 2-wide remainder
    if (t + 2 <= cnt) {
        const float4 v0 = __ldcs(&hb[(size_t)(t + 0) * EV4]);
        const float4 v1 = __ldcs(&hb[(size_t)(t + 1) * EV4]);
        upd4(v0, m1, m2);
        upd4(v1, m1, m2);
        t += 2;
    }
    if (t < cnt) {
        const float4 v0 = __ldcs(&hb[(size_t)t * EV4]);
        upd4(v0, m1, m2);
    }

    float4 r;
    if (cnt == 1) {
        r = m1;
    } else {
        r.x = 0.5f * (m1.x + ((m2.x == -INFINITY) ? NEG_INF_V : m2.x));
        r.y = 0.5f * (m1.y + ((m2.y == -INFINITY) ? NEG_INF_V : m2.y));
        r.z = 0.5f * (m1.z + ((m2.z == -INFINITY) ? NEG_INF_V : m2.z));
        r.w = 0.5f * (m1.w + ((m2.w == -INFINITY) ? NEG_INF_V : m2.w));
    }
    *o = r;
}

extern "C" void kernel_launch(void* const* d_in, const int* in_sizes, int n_in,
                              void* d_out, int out_size) {
    const float* h   = (const float*)d_in[0];
    const int*   pid = (const int*)d_in[1];
    float*       out = (float*)d_out;

    (void)in_sizes; (void)n_in; (void)out_size;

    dim3 g1((SEQ + 255) / 256, BS);
    starts_kernel<<<g1, 256>>>(pid);

    dim3 g2(PNUM, BS);
    pool_kernel<<<g2, 128>>>((const float4*)h, (float4*)out);
}